// round 10
// baseline (speedup 1.0000x reference)
#include <cuda_runtime.h>
#include <cuda_bf16.h>
#include <cstdint>

#define N_NODES 100000
#define N_EDGES 640000
#define DD      128
#define ROUNDS  4
#define SCAN_BLOCKS 98            // ceil(100000 / 1024)
#define NNDD    (N_NODES * DD)

// ---------------- scratch (allocation-free rule: __device__ globals) ----------------
// bf16-resident tensors: hi image at [0, NNDD), lo image at [NNDD, 2*NNDD)
__device__ __align__(16) __nv_bfloat16 g_statebf[2 * NNDD];
__device__ __align__(16) __nv_bfloat16 g_msgbf[2 * NNDD];
__device__ __align__(16) __nv_bfloat16 g_aggbf[2 * NNDD];
__device__ __align__(16) __nv_bfloat16 g_wb[9 * 2 * 16384];
__device__ int g_idx64;
// CSR build scratch
__device__ int g_deg[N_NODES];
__device__ int g_off[N_NODES + 1];
__device__ int g_cur[N_NODES];
__device__ int g_srcs[N_EDGES];
__device__ int g_bsum[SCAN_BLOCKS];
__device__ int g_boff[SCAN_BLOCKS];

// ---------------- edge_index dtype detection ----------------
__global__ void detect_idx_kernel(const int* __restrict__ ei32) {
    int is64 = 1;
    for (int i = 0; i < 32; i++) {
        int lo = ei32[2 * i];
        int hi = ei32[2 * i + 1];
        if (hi != 0 || lo < 0 || lo >= N_NODES) { is64 = 0; break; }
    }
    g_idx64 = is64;
}

// ---------------- CSR build (once per call) ----------------
__global__ void hist_zero_kernel() {
    int i = blockIdx.x * blockDim.x + threadIdx.x;
    if (i < N_NODES) g_deg[i] = 0;
}

__device__ __forceinline__ int edge_dst(const void* ei_raw, int e) {
    if (g_idx64) return (int)((const long long*)ei_raw)[N_EDGES + e];
    return ((const int*)ei_raw)[N_EDGES + e];
}
__device__ __forceinline__ int edge_src(const void* ei_raw, int e) {
    if (g_idx64) return (int)((const long long*)ei_raw)[e];
    return ((const int*)ei_raw)[e];
}

__global__ void hist_kernel(const void* __restrict__ ei_raw) {
    int e = blockIdx.x * blockDim.x + threadIdx.x;
    if (e >= N_EDGES) return;
    int d = edge_dst(ei_raw, e);
    if ((unsigned)d < N_NODES) atomicAdd(&g_deg[d], 1);
}

__global__ void scan1_kernel() {
    __shared__ int ss[256];
    int b = blockIdx.x, t = threadIdx.x;
    int base = b * 1024 + t * 4;
    int v[4], tot = 0;
#pragma unroll
    for (int j = 0; j < 4; j++) {
        v[j] = (base + j < N_NODES) ? g_deg[base + j] : 0;
        tot += v[j];
    }
    ss[t] = tot;
    __syncthreads();
#pragma unroll
    for (int off = 1; off < 256; off <<= 1) {
        int x = (t >= off) ? ss[t - off] : 0;
        __syncthreads();
        ss[t] += x;
        __syncthreads();
    }
    int run = ss[t] - tot;
#pragma unroll
    for (int j = 0; j < 4; j++) {
        if (base + j < N_NODES) g_off[base + j] = run;
        run += v[j];
    }
    if (t == 255) g_bsum[b] = ss[255];
}

__global__ void scan2_kernel() {
    __shared__ int ss[128];
    int t = threadIdx.x;
    int orig = (t < SCAN_BLOCKS) ? g_bsum[t] : 0;
    ss[t] = orig;
    __syncthreads();
#pragma unroll
    for (int off = 1; off < 128; off <<= 1) {
        int x = (t >= off) ? ss[t - off] : 0;
        __syncthreads();
        ss[t] += x;
        __syncthreads();
    }
    if (t < SCAN_BLOCKS) g_boff[t] = ss[t] - orig;
}

__global__ void scan3_kernel() {
    int i = blockIdx.x * blockDim.x + threadIdx.x;
    if (i < N_NODES) {
        int o = g_off[i] + g_boff[i >> 10];
        g_off[i] = o;
        g_cur[i] = o;
    }
    if (i == 0) g_off[N_NODES] = N_EDGES;
}

__global__ void fill_kernel(const void* __restrict__ ei_raw) {
    int e = blockIdx.x * blockDim.x + threadIdx.x;
    if (e >= N_EDGES) return;
    int d = edge_dst(ei_raw, e);
    int s = edge_src(ei_raw, e);
    if ((unsigned)d >= N_NODES || (unsigned)s >= N_NODES) return;
    int p = atomicAdd(&g_cur[d], 1);
    g_srcs[p] = s;
}

// ---------------- per-round aggregation (L2-bound; conversions are free here) ----------------
// reads msg hi/lo bf16, sums fp32, writes agg hi/lo bf16
__global__ __launch_bounds__(256) void aggregate_kernel() {
    int node = (blockIdx.x * 256 + threadIdx.x) >> 5;
    int lane = threadIdx.x & 31;
    if (node >= N_NODES) return;
    int beg = g_off[node], end = g_off[node + 1];
    float acc[4] = {0.f, 0.f, 0.f, 0.f};

#define GATHER(s_)                                                                    \
    {                                                                                 \
        const __nv_bfloat162* hp = (const __nv_bfloat162*)(g_msgbf + (size_t)(s_) * DD + lane * 4);        \
        const __nv_bfloat162* lp = (const __nv_bfloat162*)(g_msgbf + NNDD + (size_t)(s_) * DD + lane * 4); \
        float2 h0 = __bfloat1622float2(hp[0]);                                        \
        float2 h1 = __bfloat1622float2(hp[1]);                                        \
        float2 l0 = __bfloat1622float2(lp[0]);                                        \
        float2 l1 = __bfloat1622float2(lp[1]);                                        \
        acc[0] += h0.x + l0.x; acc[1] += h0.y + l0.y;                                 \
        acc[2] += h1.x + l1.x; acc[3] += h1.y + l1.y;                                 \
    }

    int e = beg;
    for (; e + 1 < end; e += 2) {
        int s0 = g_srcs[e], s1 = g_srcs[e + 1];
        GATHER(s0)
        GATHER(s1)
    }
    if (e < end) GATHER(g_srcs[e])
#undef GATHER

    __nv_bfloat16 h[4], l[4];
#pragma unroll
    for (int j = 0; j < 4; j++) {
        h[j] = __float2bfloat16(acc[j]);
        l[j] = __float2bfloat16(acc[j] - __bfloat162float(h[j]));
    }
    *(uint2*)(g_aggbf + (size_t)node * DD + lane * 4) = *(const uint2*)h;
    *(uint2*)(g_aggbf + NNDD + (size_t)node * DD + lane * 4) = *(const uint2*)l;
}

// ---------------- weight precompute: transpose + bf16 split ----------------
__global__ void conv_w_kernel(const float* __restrict__ Wi,
                              const float* __restrict__ Wm,
                              const float* __restrict__ Wu) {
    int m = blockIdx.x;  // 0..8
    const float* W = (m == 0) ? Wi : (m <= 4 ? Wm + (m - 1) * DD * DD : Wu + (m - 5) * DD * DD);
    __nv_bfloat16* hi = g_wb + (size_t)m * 32768;
    __nv_bfloat16* lo = hi + 16384;
    for (int i = threadIdx.x; i < 2048; i += blockDim.x) {
        int nrow = i >> 4;
        int k8   = (i & 15) * 8;
        __align__(16) __nv_bfloat16 h[8], l[8];
#pragma unroll
        for (int j = 0; j < 8; j++) {
            float w = W[(size_t)(k8 + j) * DD + nrow];   // B[n][k] = W[k][n]
            __nv_bfloat16 hb = __float2bfloat16(w);
            h[j] = hb;
            l[j] = __float2bfloat16(w - __bfloat162float(hb));
        }
        *(uint4*)(hi + nrow * DD + k8) = *(const uint4*)h;
        *(uint4*)(lo + nrow * DD + k8) = *(const uint4*)l;
    }
}

// ---------------- helpers (base-target PTX only) ----------------
__device__ __forceinline__ uint32_t smem_u32(const void* p) {
    uint32_t a;
    asm("{ .reg .u64 t; cvta.to.shared.u64 t, %1; cvt.u32.u64 %0, t; }" : "=r"(a) : "l"(p));
    return a;
}
__device__ __forceinline__ void ldsm4(uint32_t* r, uint32_t addr) {
    asm volatile("ldmatrix.sync.aligned.m8n8.x4.shared.b16 {%0,%1,%2,%3}, [%4];"
                 : "=r"(r[0]), "=r"(r[1]), "=r"(r[2]), "=r"(r[3]) : "r"(addr));
}
__device__ __forceinline__ void mma_bf16(float* c,
                                         const uint32_t* a, uint32_t b0, uint32_t b1) {
    asm volatile(
        "mma.sync.aligned.m16n8k16.row.col.f32.bf16.bf16.f32 "
        "{%0,%1,%2,%3}, {%4,%5,%6,%7}, {%8,%9}, {%0,%1,%2,%3};"
        : "+f"(c[0]), "+f"(c[1]), "+f"(c[2]), "+f"(c[3])
        : "r"(a[0]), "r"(a[1]), "r"(a[2]), "r"(a[3]), "r"(b0), "r"(b1));
}
__device__ __forceinline__ void cp_async16(uint32_t smem_addr, const void* gptr) {
    asm volatile("cp.async.ca.shared.global [%0], [%1], 16;"
                 :: "r"(smem_addr), "l"(gptr) : "memory");
}
__device__ __forceinline__ void cp_async16z(uint32_t smem_addr, const void* gptr, unsigned srcsz) {
    asm volatile("cp.async.ca.shared.global [%0], [%1], 16, %2;"
                 :: "r"(smem_addr), "l"(gptr), "r"(srcsz) : "memory");
}

// ---------------- GEMM config: 64x128 tile, 2 CTAs/SM ----------------
#define TILE_M  64
#define BSTR    136
#define A_TB    (TILE_M * BSTR * 2)       // 17408 B
#define B_TB    (128 * BSTR * 2)          // 34816 B
#define SM_BIAS 0
#define SM_AHI  512
#define SM_ALO  (SM_AHI + A_TB)
#define SM_BHI  (SM_ALO + A_TB)
#define SM_BLO  (SM_BHI + B_TB)
#define SM_TOTAL (SM_BLO + B_TB)          // 104960 B -> 2 CTAs/SM

// MODE: 0 = fresh, 1 = residual (out += ...)
// ASRC: 0 = A fp32 (convert in-kernel), 1 = A pre-split hi/lo bf16 (cp.async)
// WFP:  write fp32 result to out
// WBF:  write bf16 hi/lo result to obf (hi at obf, lo at obf + NNDD)
template <int MODE, int ASRC, int WFP, int WBF>
__global__ __launch_bounds__(256, 2) void gemm_mma_kernel(
    const float* __restrict__ A,
    const __nv_bfloat16* __restrict__ abf,
    const __nv_bfloat16* __restrict__ wb,
    const float* __restrict__ bias,
    float* __restrict__ out,
    __nv_bfloat16* __restrict__ obf,
    int n)
{
    extern __shared__ char smem[];
    const uint32_t sb = smem_u32(smem);
    const int tid = threadIdx.x, wid = tid >> 5, lane = tid & 31;
    const int wr = wid & 1, wc = wid >> 1;      // warp grid 2 (M) x 4 (N)
    const int m0 = blockIdx.x * TILE_M;

    if (tid < 128) *(float*)(smem + SM_BIAS + tid * 4) = bias[tid];

    // ---- B tiles via cp.async ----
    {
        const uint4* srch = (const uint4*)wb;
        const uint4* srcl = (const uint4*)(wb + 16384);
#pragma unroll
        for (int i = tid; i < 2048; i += 256) {
            int row = i >> 4, c = i & 15;
            uint32_t doff = (uint32_t)(row * (BSTR * 2) + c * 16);
            cp_async16(sb + SM_BHI + doff, srch + row * 16 + c);
            cp_async16(sb + SM_BLO + doff, srcl + row * 16 + c);
        }
    }

    if (ASRC == 1) {
        // ---- A tiles: pure cp.async of pre-split hi/lo (zfill beyond n) ----
#pragma unroll
        for (int i = tid; i < 1024; i += 256) {
            int r = i >> 4, c = i & 15;
            int row = m0 + r;
            int crow = row < n ? row : 0;
            unsigned sz = (row < n) ? 16u : 0u;
            uint32_t doff = (uint32_t)(r * (BSTR * 2) + c * 16);
            const __nv_bfloat16* sh = abf + (size_t)crow * DD + c * 8;
            cp_async16z(sb + SM_AHI + doff, sh, sz);
            cp_async16z(sb + SM_ALO + doff, sh + NNDD, sz);
        }
        asm volatile("cp.async.commit_group;" ::: "memory");
    } else {
        asm volatile("cp.async.commit_group;" ::: "memory");
        // ---- A tile: fp32 -> bf16 hi/lo in-kernel ----
        for (int i = tid; i < TILE_M * 16; i += 256) {
            int r  = i >> 4;
            int k8 = (i & 15) * 8;
            int row = m0 + r;
            float v[8];
            if (row < n) {
                float4 u0 = *(const float4*)(A + (size_t)row * DD + k8);
                float4 u1 = *(const float4*)(A + (size_t)row * DD + k8 + 4);
                v[0] = u0.x; v[1] = u0.y; v[2] = u0.z; v[3] = u0.w;
                v[4] = u1.x; v[5] = u1.y; v[6] = u1.z; v[7] = u1.w;
            } else {
#pragma unroll
                for (int j = 0; j < 8; j++) v[j] = 0.f;
            }
            __align__(16) __nv_bfloat16 h[8], l[8];
#pragma unroll
            for (int j = 0; j < 8; j++) {
                __nv_bfloat16 hb = __float2bfloat16(v[j]);
                h[j] = hb;
                l[j] = __float2bfloat16(v[j] - __bfloat162float(hb));
            }
            *(uint4*)(smem + SM_AHI + r * (BSTR * 2) + k8 * 2) = *(const uint4*)h;
            *(uint4*)(smem + SM_ALO + r * (BSTR * 2) + k8 * 2) = *(const uint4*)l;
        }
    }
    asm volatile("cp.async.wait_group 0;" ::: "memory");
    __syncthreads();

    // ---- mainloop: 8 k-steps, double-buffered frags ----
    float acc[2][4][4];
#pragma unroll
    for (int t = 0; t < 2; t++)
#pragma unroll
        for (int j = 0; j < 4; j++)
#pragma unroll
            for (int q = 0; q < 4; q++)
                acc[t][j][q] = 0.f;

    const uint32_t a_row  = (uint32_t)(wr * 32 + (lane & 15));
    const uint32_t a_colh = (uint32_t)(lane >> 4);
    const uint32_t b_nrow = (uint32_t)(wc * 32 + (lane & 7) + ((lane >> 4) << 3));
    const uint32_t b_kh   = (uint32_t)((lane >> 3) & 1);

    uint32_t ah[2][2][4], al[2][2][4], bh[2][2][4], bl[2][2][4];

#define LOAD_K(ks_, buf_)                                                          \
    {                                                                              \
        const uint32_t kcol = (uint32_t)((ks_) * 16);                              \
        _Pragma("unroll")                                                          \
        for (int t = 0; t < 2; t++) {                                              \
            uint32_t off = (a_row + t * 16) * (BSTR * 2) + (kcol + a_colh * 8) * 2;\
            ldsm4(ah[buf_][t], sb + SM_AHI + off);                                 \
            ldsm4(al[buf_][t], sb + SM_ALO + off);                                 \
        }                                                                          \
        _Pragma("unroll")                                                          \
        for (int p = 0; p < 2; p++) {                                              \
            uint32_t off = (b_nrow + p * 16) * (BSTR * 2) + (kcol + b_kh * 8) * 2; \
            ldsm4(bh[buf_][p], sb + SM_BHI + off);                                 \
            ldsm4(bl[buf_][p], sb + SM_BLO + off);                                 \
        }                                                                          \
    }

    LOAD_K(0, 0)
#pragma unroll
    for (int ks = 0; ks < 8; ks++) {
        const int cur = ks & 1;
        if (ks < 7) LOAD_K(ks + 1, cur ^ 1)
#pragma unroll
        for (int t = 0; t < 2; t++) {
#pragma unroll
            for (int j = 0; j < 4; j++) {
                uint32_t b0h = bh[cur][j >> 1][(j & 1) * 2], b1h = bh[cur][j >> 1][(j & 1) * 2 + 1];
                uint32_t b0l = bl[cur][j >> 1][(j & 1) * 2], b1l = bl[cur][j >> 1][(j & 1) * 2 + 1];
                float* c = acc[t][j];
                mma_bf16(c, ah[cur][t], b0h, b1h);
                mma_bf16(c, ah[cur][t], b0l, b1l);
                mma_bf16(c, al[cur][t], b0h, b1h);
            }
        }
    }
#undef LOAD_K

    // ---- epilogue: bias + relu (+ residual), write fp32 and/or bf16 hi/lo ----
    const float* bs = (const float*)(smem + SM_BIAS);
#pragma unroll
    for (int t = 0; t < 2; t++) {
        int row0 = m0 + wr * 32 + t * 16 + (lane >> 2);
#pragma unroll
        for (int half = 0; half < 2; half++) {
            int row = row0 + half * 8;
            if (row >= n) continue;
#pragma unroll
            for (int j = 0; j < 4; j++) {
                int col = wc * 32 + j * 8 + (lane & 3) * 2;
                float v0 = acc[t][j][half * 2 + 0] + bs[col];
                float v1 = acc[t][j][half * 2 + 1] + bs[col + 1];
                v0 = v0 > 0.f ? v0 : 0.f;
                v1 = v1 > 0.f ? v1 : 0.f;
                if (MODE == 1) {
                    float2 o = *(const float2*)(out + (size_t)row * DD + col);
                    v0 += o.x; v1 += o.y;
                }
                if (WFP)
                    *(float2*)(out + (size_t)row * DD + col) = make_float2(v0, v1);
                if (WBF) {
                    __nv_bfloat16 h0 = __float2bfloat16(v0);
                    __nv_bfloat16 h1 = __float2bfloat16(v1);
                    __nv_bfloat16 l0 = __float2bfloat16(v0 - __bfloat162float(h0));
                    __nv_bfloat16 l1 = __float2bfloat16(v1 - __bfloat162float(h1));
                    __nv_bfloat16 hh[2] = {h0, h1}, ll[2] = {l0, l1};
                    *(uint32_t*)(obf + (size_t)row * DD + col) = *(const uint32_t*)hh;
                    *(uint32_t*)(obf + NNDD + (size_t)row * DD + col) = *(const uint32_t*)ll;
                }
            }
        }
    }
}

// ---------------- launcher ----------------
extern "C" void kernel_launch(void* const* d_in, const int* in_sizes, int n_in,
                              void* d_out, int out_size)
{
    const float* x  = (const float*)d_in[0];
    const void*  ei = d_in[1];
    const float* Wi = (const float*)d_in[2];
    const float* bi = (const float*)d_in[3];
    const float* Wm = (const float*)d_in[4];
    const float* bm = (const float*)d_in[5];
    const float* Wu = (const float*)d_in[6];
    const float* bu = (const float*)d_in[7];
    float* out = (float*)d_out;

    cudaFuncSetAttribute(gemm_mma_kernel<0,0,1,1>, cudaFuncAttributeMaxDynamicSharedMemorySize, SM_TOTAL);
    cudaFuncSetAttribute(gemm_mma_kernel<0,1,0,1>, cudaFuncAttributeMaxDynamicSharedMemorySize, SM_TOTAL);
    cudaFuncSetAttribute(gemm_mma_kernel<1,1,1,1>, cudaFuncAttributeMaxDynamicSharedMemorySize, SM_TOTAL);

    __nv_bfloat16 *wb, *statebf, *msgbf, *aggbf;
    cudaGetSymbolAddress((void**)&wb, g_wb);
    cudaGetSymbolAddress((void**)&statebf, g_statebf);
    cudaGetSymbolAddress((void**)&msgbf, g_msgbf);
    cudaGetSymbolAddress((void**)&aggbf, g_aggbf);

    dim3 grid((N_NODES + TILE_M - 1) / TILE_M);

    detect_idx_kernel<<<1, 1>>>((const int*)ei);
    conv_w_kernel<<<9, 256>>>(Wi, Wm, Wu);

    // ---- CSR build (once per call) ----
    hist_zero_kernel<<<(N_NODES + 255) / 256, 256>>>();
    hist_kernel<<<(N_EDGES + 255) / 256, 256>>>(ei);
    scan1_kernel<<<SCAN_BLOCKS, 256>>>();
    scan2_kernel<<<1, 128>>>();
    scan3_kernel<<<(N_NODES + 255) / 256, 256>>>();
    fill_kernel<<<(N_EDGES + 255) / 256, 256>>>(ei);

    // state = relu(x @ Wi + bi): fp32 A, write fp32 out + bf16 state
    gemm_mma_kernel<0,0,1,1><<<grid, 256, SM_TOTAL>>>(x, nullptr, wb, bi, out, statebf, N_NODES);

    for (int r = 0; r < ROUNDS; r++) {
        // message = relu(state @ Wm_r + bm_r): bf16 A, write bf16 msg only
        gemm_mma_kernel<0,1,0,1><<<grid, 256, SM_TOTAL>>>(
            nullptr, statebf, wb + (size_t)(1 + r) * 32768, bm + r * DD, out, msgbf, N_NODES);
        // aggregated = segment_sum(msg[src], dst): bf16 in/out, fp32 accum
        aggregate_kernel<<<(N_NODES * 32 + 255) / 256, 256>>>();
        // state = state + relu(agg @ Wu_r + bu_r): bf16 A, residual, write fp32 + bf16 state
        gemm_mma_kernel<1,1,1,1><<<grid, 256, SM_TOTAL>>>(
            nullptr, aggbf, wb + (size_t)(5 + r) * 32768, bu + r * DD, out, statebf, N_NODES);
    }
}

// round 11
// speedup vs baseline: 1.1844x; 1.1844x over previous
#include <cuda_runtime.h>
#include <cuda_bf16.h>
#include <cstdint>

#define N_NODES 100000
#define N_EDGES 640000
#define DD      128
#define ROUNDS  4
#define SCAN_BLOCKS 98            // ceil(100000 / 1024)

// ---------------- scratch (allocation-free rule: __device__ globals) ----------------
__device__ __align__(16) float g_msg[N_NODES * DD];
__device__ __align__(16) float g_agg[N_NODES * DD];
__device__ __align__(16) __nv_bfloat16 g_wb[9 * 2 * 16384];
__device__ int g_idx64;
// CSR build scratch
__device__ int g_deg[N_NODES];
__device__ int g_off[N_NODES + 1];
__device__ int g_cur[N_NODES];
__device__ int g_srcs[N_EDGES];
__device__ int g_bsum[SCAN_BLOCKS];
__device__ int g_boff[SCAN_BLOCKS];

// ---------------- edge_index dtype detection ----------------
__global__ void detect_idx_kernel(const int* __restrict__ ei32) {
    int is64 = 1;
    for (int i = 0; i < 32; i++) {
        int lo = ei32[2 * i];
        int hi = ei32[2 * i + 1];
        if (hi != 0 || lo < 0 || lo >= N_NODES) { is64 = 0; break; }
    }
    g_idx64 = is64;
}

// ---------------- CSR build (once per call, overlapped with first GEMMs) ----------------
__global__ void hist_zero_kernel() {
    int i = blockIdx.x * blockDim.x + threadIdx.x;
    if (i < N_NODES) g_deg[i] = 0;
}

__device__ __forceinline__ int edge_dst(const void* ei_raw, int e) {
    if (g_idx64) return (int)((const long long*)ei_raw)[N_EDGES + e];
    return ((const int*)ei_raw)[N_EDGES + e];
}
__device__ __forceinline__ int edge_src(const void* ei_raw, int e) {
    if (g_idx64) return (int)((const long long*)ei_raw)[e];
    return ((const int*)ei_raw)[e];
}

__global__ void hist_kernel(const void* __restrict__ ei_raw) {
    int e = blockIdx.x * blockDim.x + threadIdx.x;
    if (e >= N_EDGES) return;
    int d = edge_dst(ei_raw, e);
    if ((unsigned)d < N_NODES) atomicAdd(&g_deg[d], 1);
}

__global__ void scan1_kernel() {
    __shared__ int ss[256];
    int b = blockIdx.x, t = threadIdx.x;
    int base = b * 1024 + t * 4;
    int v[4], tot = 0;
#pragma unroll
    for (int j = 0; j < 4; j++) {
        v[j] = (base + j < N_NODES) ? g_deg[base + j] : 0;
        tot += v[j];
    }
    ss[t] = tot;
    __syncthreads();
#pragma unroll
    for (int off = 1; off < 256; off <<= 1) {
        int x = (t >= off) ? ss[t - off] : 0;
        __syncthreads();
        ss[t] += x;
        __syncthreads();
    }
    int run = ss[t] - tot;
#pragma unroll
    for (int j = 0; j < 4; j++) {
        if (base + j < N_NODES) g_off[base + j] = run;
        run += v[j];
    }
    if (t == 255) g_bsum[b] = ss[255];
}

__global__ void scan2_kernel() {
    __shared__ int ss[128];
    int t = threadIdx.x;
    int orig = (t < SCAN_BLOCKS) ? g_bsum[t] : 0;
    ss[t] = orig;
    __syncthreads();
#pragma unroll
    for (int off = 1; off < 128; off <<= 1) {
        int x = (t >= off) ? ss[t - off] : 0;
        __syncthreads();
        ss[t] += x;
        __syncthreads();
    }
    if (t < SCAN_BLOCKS) g_boff[t] = ss[t] - orig;
}

__global__ void scan3_kernel() {
    int i = blockIdx.x * blockDim.x + threadIdx.x;
    if (i < N_NODES) {
        int o = g_off[i] + g_boff[i >> 10];
        g_off[i] = o;
        g_cur[i] = o;
    }
    if (i == 0) g_off[N_NODES] = N_EDGES;
}

__global__ void fill_kernel(const void* __restrict__ ei_raw) {
    int e = blockIdx.x * blockDim.x + threadIdx.x;
    if (e >= N_EDGES) return;
    int d = edge_dst(ei_raw, e);
    int s = edge_src(ei_raw, e);
    if ((unsigned)d >= N_NODES || (unsigned)s >= N_NODES) return;
    int p = atomicAdd(&g_cur[d], 1);
    g_srcs[p] = s;
}

// ---------------- per-round aggregation: warp per dst node (LTS-roofline) ----------------
__global__ __launch_bounds__(256) void aggregate_kernel() {
    int node = (blockIdx.x * 256 + threadIdx.x) >> 5;
    int lane = threadIdx.x & 31;
    if (node >= N_NODES) return;
    int beg = g_off[node], end = g_off[node + 1];
    float4 acc = make_float4(0.f, 0.f, 0.f, 0.f);
    int e = beg;
    for (; e + 1 < end; e += 2) {
        int s0 = g_srcs[e], s1 = g_srcs[e + 1];
        float4 v0 = *(const float4*)(g_msg + (size_t)s0 * DD + lane * 4);
        float4 v1 = *(const float4*)(g_msg + (size_t)s1 * DD + lane * 4);
        acc.x += v0.x; acc.y += v0.y; acc.z += v0.z; acc.w += v0.w;
        acc.x += v1.x; acc.y += v1.y; acc.z += v1.z; acc.w += v1.w;
    }
    if (e < end) {
        float4 v = *(const float4*)(g_msg + (size_t)g_srcs[e] * DD + lane * 4);
        acc.x += v.x; acc.y += v.y; acc.z += v.z; acc.w += v.w;
    }
    *(float4*)(g_agg + (size_t)node * DD + lane * 4) = acc;
}

// ---------------- weight precompute: transpose + bf16 split ----------------
__global__ void conv_w_kernel(const float* __restrict__ Wi,
                              const float* __restrict__ Wm,
                              const float* __restrict__ Wu) {
    int m = blockIdx.x;  // 0..8
    const float* W = (m == 0) ? Wi : (m <= 4 ? Wm + (m - 1) * DD * DD : Wu + (m - 5) * DD * DD);
    __nv_bfloat16* hi = g_wb + (size_t)m * 32768;
    __nv_bfloat16* lo = hi + 16384;
    for (int i = threadIdx.x; i < 2048; i += blockDim.x) {
        int nrow = i >> 4;
        int k8   = (i & 15) * 8;
        __align__(16) __nv_bfloat16 h[8], l[8];
#pragma unroll
        for (int j = 0; j < 8; j++) {
            float w = W[(size_t)(k8 + j) * DD + nrow];   // B[n][k] = W[k][n]
            __nv_bfloat16 hb = __float2bfloat16(w);
            h[j] = hb;
            l[j] = __float2bfloat16(w - __bfloat162float(hb));
        }
        *(uint4*)(hi + nrow * DD + k8) = *(const uint4*)h;
        *(uint4*)(lo + nrow * DD + k8) = *(const uint4*)l;
    }
}

// ---------------- helpers (base-target PTX only) ----------------
__device__ __forceinline__ uint32_t smem_u32(const void* p) {
    uint32_t a;
    asm("{ .reg .u64 t; cvta.to.shared.u64 t, %1; cvt.u32.u64 %0, t; }" : "=r"(a) : "l"(p));
    return a;
}
__device__ __forceinline__ void ldsm4(uint32_t* r, uint32_t addr) {
    asm volatile("ldmatrix.sync.aligned.m8n8.x4.shared.b16 {%0,%1,%2,%3}, [%4];"
                 : "=r"(r[0]), "=r"(r[1]), "=r"(r[2]), "=r"(r[3]) : "r"(addr));
}
__device__ __forceinline__ void mma_bf16(float* c,
                                         const uint32_t* a, uint32_t b0, uint32_t b1) {
    asm volatile(
        "mma.sync.aligned.m16n8k16.row.col.f32.bf16.bf16.f32 "
        "{%0,%1,%2,%3}, {%4,%5,%6,%7}, {%8,%9}, {%0,%1,%2,%3};"
        : "+f"(c[0]), "+f"(c[1]), "+f"(c[2]), "+f"(c[3])
        : "r"(a[0]), "r"(a[1]), "r"(a[2]), "r"(a[3]), "r"(b0), "r"(b1));
}
__device__ __forceinline__ void cp_async16(uint32_t smem_addr, const void* gptr) {
    asm volatile("cp.async.ca.shared.global [%0], [%1], 16;"
                 :: "r"(smem_addr), "l"(gptr) : "memory");
}

// ---------------- GEMM: 64x128 tile, 2 CTAs/SM, pipelined frags (R7 config) ----------------
#define TILE_M  64
#define BSTR    136
#define A_TB    (TILE_M * BSTR * 2)       // 17408 B
#define B_TB    (128 * BSTR * 2)          // 34816 B
#define SM_BIAS 0
#define SM_AHI  512
#define SM_ALO  (SM_AHI + A_TB)
#define SM_BHI  (SM_ALO + A_TB)
#define SM_BLO  (SM_BHI + B_TB)
#define SM_TOTAL (SM_BLO + B_TB)          // 104960 B -> 2 CTAs/SM

template <int MODE>
__global__ __launch_bounds__(256, 2) void gemm_mma_kernel(
    const float* __restrict__ A,
    const __nv_bfloat16* __restrict__ wb,
    const float* __restrict__ bias,
    float* __restrict__ out,
    int n)
{
    extern __shared__ char smem[];
    const uint32_t sb = smem_u32(smem);
    const int tid = threadIdx.x, wid = tid >> 5, lane = tid & 31;
    const int wr = wid & 1, wc = wid >> 1;      // warp grid 2 (M) x 4 (N)
    const int m0 = blockIdx.x * TILE_M;

    if (tid < 128) *(float*)(smem + SM_BIAS + tid * 4) = bias[tid];

    // ---- B tiles via cp.async (overlaps with A conversion below) ----
    {
        const uint4* srch = (const uint4*)wb;
        const uint4* srcl = (const uint4*)(wb + 16384);
#pragma unroll
        for (int i = tid; i < 2048; i += 256) {
            int row = i >> 4, c = i & 15;
            uint32_t doff = (uint32_t)(row * (BSTR * 2) + c * 16);
            cp_async16(sb + SM_BHI + doff, srch + row * 16 + c);
            cp_async16(sb + SM_BLO + doff, srcl + row * 16 + c);
        }
        asm volatile("cp.async.commit_group;" ::: "memory");
    }

    // ---- A tile (64 rows): fp32 -> bf16 hi/lo ----
    for (int i = tid; i < TILE_M * 16; i += 256) {
        int r  = i >> 4;
        int k8 = (i & 15) * 8;
        int row = m0 + r;
        float v[8];
        if (row < n) {
            float4 u0 = *(const float4*)(A + (size_t)row * DD + k8);
            float4 u1 = *(const float4*)(A + (size_t)row * DD + k8 + 4);
            v[0] = u0.x; v[1] = u0.y; v[2] = u0.z; v[3] = u0.w;
            v[4] = u1.x; v[5] = u1.y; v[6] = u1.z; v[7] = u1.w;
        } else {
#pragma unroll
            for (int j = 0; j < 8; j++) v[j] = 0.f;
        }
        __align__(16) __nv_bfloat16 h[8], l[8];
#pragma unroll
        for (int j = 0; j < 8; j++) {
            __nv_bfloat16 hb = __float2bfloat16(v[j]);
            h[j] = hb;
            l[j] = __float2bfloat16(v[j] - __bfloat162float(hb));
        }
        *(uint4*)(smem + SM_AHI + r * (BSTR * 2) + k8 * 2) = *(const uint4*)h;
        *(uint4*)(smem + SM_ALO + r * (BSTR * 2) + k8 * 2) = *(const uint4*)l;
    }
    asm volatile("cp.async.wait_group 0;" ::: "memory");
    __syncthreads();

    // ---- mainloop: 8 k-steps, double-buffered frags ----
    float acc[2][4][4];
#pragma unroll
    for (int t = 0; t < 2; t++)
#pragma unroll
        for (int j = 0; j < 4; j++)
#pragma unroll
            for (int q = 0; q < 4; q++)
                acc[t][j][q] = 0.f;

    const uint32_t a_row  = (uint32_t)(wr * 32 + (lane & 15));
    const uint32_t a_colh = (uint32_t)(lane >> 4);
    const uint32_t b_nrow = (uint32_t)(wc * 32 + (lane & 7) + ((lane >> 4) << 3));
    const uint32_t b_kh   = (uint32_t)((lane >> 3) & 1);

    uint32_t ah[2][2][4], al[2][2][4], bh[2][2][4], bl[2][2][4];

#define LOAD_K(ks_, buf_)                                                          \
    {                                                                              \
        const uint32_t kcol = (uint32_t)((ks_) * 16);                              \
        _Pragma("unroll")                                                          \
        for (int t = 0; t < 2; t++) {                                              \
            uint32_t off = (a_row + t * 16) * (BSTR * 2) + (kcol + a_colh * 8) * 2;\
            ldsm4(ah[buf_][t], sb + SM_AHI + off);                                 \
            ldsm4(al[buf_][t], sb + SM_ALO + off);                                 \
        }                                                                          \
        _Pragma("unroll")                                                          \
        for (int p = 0; p < 2; p++) {                                              \
            uint32_t off = (b_nrow + p * 16) * (BSTR * 2) + (kcol + b_kh * 8) * 2; \
            ldsm4(bh[buf_][p], sb + SM_BHI + off);                                 \
            ldsm4(bl[buf_][p], sb + SM_BLO + off);                                 \
        }                                                                          \
    }

    LOAD_K(0, 0)
#pragma unroll
    for (int ks = 0; ks < 8; ks++) {
        const int cur = ks & 1;
        if (ks < 7) LOAD_K(ks + 1, cur ^ 1)
#pragma unroll
        for (int t = 0; t < 2; t++) {
#pragma unroll
            for (int j = 0; j < 4; j++) {
                uint32_t b0h = bh[cur][j >> 1][(j & 1) * 2], b1h = bh[cur][j >> 1][(j & 1) * 2 + 1];
                uint32_t b0l = bl[cur][j >> 1][(j & 1) * 2], b1l = bl[cur][j >> 1][(j & 1) * 2 + 1];
                float* c = acc[t][j];
                mma_bf16(c, ah[cur][t], b0h, b1h);
                mma_bf16(c, ah[cur][t], b0l, b1l);
                mma_bf16(c, al[cur][t], b0h, b1h);
            }
        }
    }
#undef LOAD_K

    // ---- epilogue: bias + relu (+ residual) ----
    const float* bs = (const float*)(smem + SM_BIAS);
#pragma unroll
    for (int t = 0; t < 2; t++) {
        int row0 = m0 + wr * 32 + t * 16 + (lane >> 2);
#pragma unroll
        for (int half = 0; half < 2; half++) {
            int row = row0 + half * 8;
            if (row >= n) continue;
            float* orow = out + (size_t)row * DD;
#pragma unroll
            for (int j = 0; j < 4; j++) {
                int col = wc * 32 + j * 8 + (lane & 3) * 2;
                float v0 = acc[t][j][half * 2 + 0] + bs[col];
                float v1 = acc[t][j][half * 2 + 1] + bs[col + 1];
                v0 = v0 > 0.f ? v0 : 0.f;
                v1 = v1 > 0.f ? v1 : 0.f;
                if (MODE == 1) {
                    float2 o = *(const float2*)(orow + col);
                    v0 += o.x; v1 += o.y;
                }
                *(float2*)(orow + col) = make_float2(v0, v1);
            }
        }
    }
}

// ---------------- launcher: CSR build forked onto a side stream ----------------
extern "C" void kernel_launch(void* const* d_in, const int* in_sizes, int n_in,
                              void* d_out, int out_size)
{
    const float* x  = (const float*)d_in[0];
    const void*  ei = d_in[1];
    const float* Wi = (const float*)d_in[2];
    const float* bi = (const float*)d_in[3];
    const float* Wm = (const float*)d_in[4];
    const float* bm = (const float*)d_in[5];
    const float* Wu = (const float*)d_in[6];
    const float* bu = (const float*)d_in[7];
    float* out = (float*)d_out;

    cudaFuncSetAttribute(gemm_mma_kernel<0>, cudaFuncAttributeMaxDynamicSharedMemorySize, SM_TOTAL);
    cudaFuncSetAttribute(gemm_mma_kernel<1>, cudaFuncAttributeMaxDynamicSharedMemorySize, SM_TOTAL);

    float *msg, *agg;
    __nv_bfloat16* wb;
    cudaGetSymbolAddress((void**)&msg, g_msg);
    cudaGetSymbolAddress((void**)&agg, g_agg);
    cudaGetSymbolAddress((void**)&wb, g_wb);

    dim3 grid((N_NODES + TILE_M - 1) / TILE_M);

    // Fork: CSR build runs on a side stream, overlapped with the first two GEMMs.
    // (streams/events are host objects — no tracked device allocation; not destroyed
    //  because they become part of the captured graph's lifetime)
    cudaStream_t s2;
    cudaStreamCreateWithFlags(&s2, cudaStreamNonBlocking);
    cudaEvent_t e0, e1;
    cudaEventCreateWithFlags(&e0, cudaEventDisableTiming);
    cudaEventCreateWithFlags(&e1, cudaEventDisableTiming);

    cudaEventRecord(e0, 0);
    cudaStreamWaitEvent(s2, e0, 0);
    detect_idx_kernel<<<1, 1, 0, s2>>>((const int*)ei);
    hist_zero_kernel<<<(N_NODES + 255) / 256, 256, 0, s2>>>();
    hist_kernel<<<(N_EDGES + 255) / 256, 256, 0, s2>>>(ei);
    scan1_kernel<<<SCAN_BLOCKS, 256, 0, s2>>>();
    scan2_kernel<<<1, 128, 0, s2>>>();
    scan3_kernel<<<(N_NODES + 255) / 256, 256, 0, s2>>>();
    fill_kernel<<<(N_EDGES + 255) / 256, 256, 0, s2>>>(ei);
    cudaEventRecord(e1, s2);

    // Main chain
    conv_w_kernel<<<9, 256>>>(Wi, Wm, Wu);

    // state = relu(x @ Wi + bi)
    gemm_mma_kernel<0><<<grid, 256, SM_TOTAL>>>(x, wb, bi, out, N_NODES);

    for (int r = 0; r < ROUNDS; r++) {
        // message = relu(state @ Wm_r + bm_r)
        gemm_mma_kernel<0><<<grid, 256, SM_TOTAL>>>(out, wb + (size_t)(1 + r) * 32768,
                                                    bm + r * DD, msg, N_NODES);
        if (r == 0) cudaStreamWaitEvent(0, e1, 0);   // join: CSR must be built
        // aggregated = segment_sum(message[src], dst)  (CSR, no atomics, LTS-roofline)
        aggregate_kernel<<<(N_NODES * 32 + 255) / 256, 256>>>();
        // state = state + relu(aggregated @ Wu_r + bu_r)
        gemm_mma_kernel<1><<<grid, 256, SM_TOTAL>>>(agg, wb + (size_t)(5 + r) * 32768,
                                                    bu + r * DD, out, N_NODES);
    }
}

// round 13
// speedup vs baseline: 1.2907x; 1.0898x over previous
#include <cuda_runtime.h>
#include <cuda_bf16.h>
#include <cstdint>

#define N_NODES 100000
#define N_EDGES 640000
#define DD      128
#define ROUNDS  4
#define SCAN_BLOCKS 98            // ceil(100000 / 1024)

// chunking: 1563 M-blocks total -> 782 (rows [0,50048)) + 781 (rows [50048,100000))
#define CHUNK_BLKS0 782
#define CHUNK_BLKS1 781
#define CHUNK_ROWS0 50048

// ---------------- scratch (allocation-free rule: __device__ globals) ----------------
__device__ __align__(16) float g_msg[N_NODES * DD];
__device__ __align__(16) float g_agg[N_NODES * DD];
__device__ __align__(16) __nv_bfloat16 g_wb[9 * 2 * 16384];
__device__ int g_idx64;
// CSR build scratch
__device__ int g_deg[N_NODES];
__device__ int g_off[N_NODES + 1];
__device__ int g_cur[N_NODES];
__device__ int g_srcs[N_EDGES];
__device__ int g_bsum[SCAN_BLOCKS];
__device__ int g_boff[SCAN_BLOCKS];

// ---------------- edge_index dtype detection ----------------
__global__ void detect_idx_kernel(const int* __restrict__ ei32) {
    int is64 = 1;
    for (int i = 0; i < 32; i++) {
        int lo = ei32[2 * i];
        int hi = ei32[2 * i + 1];
        if (hi != 0 || lo < 0 || lo >= N_NODES) { is64 = 0; break; }
    }
    g_idx64 = is64;
}

// ---------------- CSR build (once per call, overlapped with first GEMMs) ----------------
__global__ void hist_zero_kernel() {
    int i = blockIdx.x * blockDim.x + threadIdx.x;
    if (i < N_NODES) g_deg[i] = 0;
}

__device__ __forceinline__ int edge_dst(const void* ei_raw, int e) {
    if (g_idx64) return (int)((const long long*)ei_raw)[N_EDGES + e];
    return ((const int*)ei_raw)[N_EDGES + e];
}
__device__ __forceinline__ int edge_src(const void* ei_raw, int e) {
    if (g_idx64) return (int)((const long long*)ei_raw)[e];
    return ((const int*)ei_raw)[e];
}

__global__ void hist_kernel(const void* __restrict__ ei_raw) {
    int e = blockIdx.x * blockDim.x + threadIdx.x;
    if (e >= N_EDGES) return;
    int d = edge_dst(ei_raw, e);
    if ((unsigned)d < N_NODES) atomicAdd(&g_deg[d], 1);
}

__global__ void scan1_kernel() {
    __shared__ int ss[256];
    int b = blockIdx.x, t = threadIdx.x;
    int base = b * 1024 + t * 4;
    int v[4], tot = 0;
#pragma unroll
    for (int j = 0; j < 4; j++) {
        v[j] = (base + j < N_NODES) ? g_deg[base + j] : 0;
        tot += v[j];
    }
    ss[t] = tot;
    __syncthreads();
#pragma unroll
    for (int off = 1; off < 256; off <<= 1) {
        int x = (t >= off) ? ss[t - off] : 0;
        __syncthreads();
        ss[t] += x;
        __syncthreads();
    }
    int run = ss[t] - tot;
#pragma unroll
    for (int j = 0; j < 4; j++) {
        if (base + j < N_NODES) g_off[base + j] = run;
        run += v[j];
    }
    if (t == 255) g_bsum[b] = ss[255];
}

__global__ void scan2_kernel() {
    __shared__ int ss[128];
    int t = threadIdx.x;
    int orig = (t < SCAN_BLOCKS) ? g_bsum[t] : 0;
    ss[t] = orig;
    __syncthreads();
#pragma unroll
    for (int off = 1; off < 128; off <<= 1) {
        int x = (t >= off) ? ss[t - off] : 0;
        __syncthreads();
        ss[t] += x;
        __syncthreads();
    }
    if (t < SCAN_BLOCKS) g_boff[t] = ss[t] - orig;
}

__global__ void scan3_kernel() {
    int i = blockIdx.x * blockDim.x + threadIdx.x;
    if (i < N_NODES) {
        int o = g_off[i] + g_boff[i >> 10];
        g_off[i] = o;
        g_cur[i] = o;
    }
    if (i == 0) g_off[N_NODES] = N_EDGES;
}

__global__ void fill_kernel(const void* __restrict__ ei_raw) {
    int e = blockIdx.x * blockDim.x + threadIdx.x;
    if (e >= N_EDGES) return;
    int d = edge_dst(ei_raw, e);
    int s = edge_src(ei_raw, e);
    if ((unsigned)d >= N_NODES || (unsigned)s >= N_NODES) return;
    int p = atomicAdd(&g_cur[d], 1);
    g_srcs[p] = s;
}

// ---------------- per-round aggregation for a node range (LTS-roofline) ----------------
__global__ __launch_bounds__(256) void aggregate_kernel(int node_lo, int node_hi) {
    int node = node_lo + ((blockIdx.x * 256 + threadIdx.x) >> 5);
    int lane = threadIdx.x & 31;
    if (node >= node_hi) return;
    int beg = g_off[node], end = g_off[node + 1];
    float4 acc = make_float4(0.f, 0.f, 0.f, 0.f);
    int e = beg;
    for (; e + 1 < end; e += 2) {
        int s0 = g_srcs[e], s1 = g_srcs[e + 1];
        float4 v0 = *(const float4*)(g_msg + (size_t)s0 * DD + lane * 4);
        float4 v1 = *(const float4*)(g_msg + (size_t)s1 * DD + lane * 4);
        acc.x += v0.x; acc.y += v0.y; acc.z += v0.z; acc.w += v0.w;
        acc.x += v1.x; acc.y += v1.y; acc.z += v1.z; acc.w += v1.w;
    }
    if (e < end) {
        float4 v = *(const float4*)(g_msg + (size_t)g_srcs[e] * DD + lane * 4);
        acc.x += v.x; acc.y += v.y; acc.z += v.z; acc.w += v.w;
    }
    *(float4*)(g_agg + (size_t)node * DD + lane * 4) = acc;
}

// ---------------- weight precompute: transpose + bf16 split ----------------
__global__ void conv_w_kernel(const float* __restrict__ Wi,
                              const float* __restrict__ Wm,
                              const float* __restrict__ Wu) {
    int m = blockIdx.x;  // 0..8
    const float* W = (m == 0) ? Wi : (m <= 4 ? Wm + (m - 1) * DD * DD : Wu + (m - 5) * DD * DD);
    __nv_bfloat16* hi = g_wb + (size_t)m * 32768;
    __nv_bfloat16* lo = hi + 16384;
    for (int i = threadIdx.x; i < 2048; i += blockDim.x) {
        int nrow = i >> 4;
        int k8   = (i & 15) * 8;
        __align__(16) __nv_bfloat16 h[8], l[8];
#pragma unroll
        for (int j = 0; j < 8; j++) {
            float w = W[(size_t)(k8 + j) * DD + nrow];   // B[n][k] = W[k][n]
            __nv_bfloat16 hb = __float2bfloat16(w);
            h[j] = hb;
            l[j] = __float2bfloat16(w - __bfloat162float(hb));
        }
        *(uint4*)(hi + nrow * DD + k8) = *(const uint4*)h;
        *(uint4*)(lo + nrow * DD + k8) = *(const uint4*)l;
    }
}

// ---------------- helpers (base-target PTX only) ----------------
__device__ __forceinline__ uint32_t smem_u32(const void* p) {
    uint32_t a;
    asm("{ .reg .u64 t; cvta.to.shared.u64 t, %1; cvt.u32.u64 %0, t; }" : "=r"(a) : "l"(p));
    return a;
}
__device__ __forceinline__ void ldsm4(uint32_t* r, uint32_t addr) {
    asm volatile("ldmatrix.sync.aligned.m8n8.x4.shared.b16 {%0,%1,%2,%3}, [%4];"
                 : "=r"(r[0]), "=r"(r[1]), "=r"(r[2]), "=r"(r[3]) : "r"(addr));
}
__device__ __forceinline__ void mma_bf16(float* c,
                                         const uint32_t* a, uint32_t b0, uint32_t b1) {
    asm volatile(
        "mma.sync.aligned.m16n8k16.row.col.f32.bf16.bf16.f32 "
        "{%0,%1,%2,%3}, {%4,%5,%6,%7}, {%8,%9}, {%0,%1,%2,%3};"
        : "+f"(c[0]), "+f"(c[1]), "+f"(c[2]), "+f"(c[3])
        : "r"(a[0]), "r"(a[1]), "r"(a[2]), "r"(a[3]), "r"(b0), "r"(b1));
}
__device__ __forceinline__ void cp_async16(uint32_t smem_addr, const void* gptr) {
    asm volatile("cp.async.ca.shared.global [%0], [%1], 16;"
                 :: "r"(smem_addr), "l"(gptr) : "memory");
}

// ---------------- GEMM: 64x128 tile, 2 CTAs/SM, pipelined frags ----------------
#define TILE_M  64
#define BSTR    136
#define A_TB    (TILE_M * BSTR * 2)       // 17408 B
#define B_TB    (128 * BSTR * 2)          // 34816 B
#define SM_BIAS 0
#define SM_AHI  512
#define SM_ALO  (SM_AHI + A_TB)
#define SM_BHI  (SM_ALO + A_TB)
#define SM_BLO  (SM_BHI + B_TB)
#define SM_TOTAL (SM_BLO + B_TB)          // 104960 B -> 2 CTAs/SM

template <int MODE>
__global__ __launch_bounds__(256, 2) void gemm_mma_kernel(
    const float* __restrict__ A,
    const __nv_bfloat16* __restrict__ wb,
    const float* __restrict__ bias,
    float* __restrict__ out,
    int n, int mb0)
{
    extern __shared__ char smem[];
    const uint32_t sb = smem_u32(smem);
    const int tid = threadIdx.x, wid = tid >> 5, lane = tid & 31;
    const int wr = wid & 1, wc = wid >> 1;      // warp grid 2 (M) x 4 (N)
    const int m0 = (blockIdx.x + mb0) * TILE_M;

    if (tid < 128) *(float*)(smem + SM_BIAS + tid * 4) = bias[tid];

    // ---- B tiles via cp.async ----
    {
        const uint4* srch = (const uint4*)wb;
        const uint4* srcl = (const uint4*)(wb + 16384);
#pragma unroll
        for (int i = tid; i < 2048; i += 256) {
            int row = i >> 4, c = i & 15;
            uint32_t doff = (uint32_t)(row * (BSTR * 2) + c * 16);
            cp_async16(sb + SM_BHI + doff, srch + row * 16 + c);
            cp_async16(sb + SM_BLO + doff, srcl + row * 16 + c);
        }
        asm volatile("cp.async.commit_group;" ::: "memory");
    }

    // ---- A tile (64 rows): fp32 -> bf16 hi/lo ----
    for (int i = tid; i < TILE_M * 16; i += 256) {
        int r  = i >> 4;
        int k8 = (i & 15) * 8;
        int row = m0 + r;
        float v[8];
        if (row < n) {
            float4 u0 = *(const float4*)(A + (size_t)row * DD + k8);
            float4 u1 = *(const float4*)(A + (size_t)row * DD + k8 + 4);
            v[0] = u0.x; v[1] = u0.y; v[2] = u0.z; v[3] = u0.w;
            v[4] = u1.x; v[5] = u1.y; v[6] = u1.z; v[7] = u1.w;
        } else {
#pragma unroll
            for (int j = 0; j < 8; j++) v[j] = 0.f;
        }
        __align__(16) __nv_bfloat16 h[8], l[8];
#pragma unroll
        for (int j = 0; j < 8; j++) {
            __nv_bfloat16 hb = __float2bfloat16(v[j]);
            h[j] = hb;
            l[j] = __float2bfloat16(v[j] - __bfloat162float(hb));
        }
        *(uint4*)(smem + SM_AHI + r * (BSTR * 2) + k8 * 2) = *(const uint4*)h;
        *(uint4*)(smem + SM_ALO + r * (BSTR * 2) + k8 * 2) = *(const uint4*)l;
    }
    asm volatile("cp.async.wait_group 0;" ::: "memory");
    __syncthreads();

    // ---- mainloop: 8 k-steps, double-buffered frags ----
    float acc[2][4][4];
#pragma unroll
    for (int t = 0; t < 2; t++)
#pragma unroll
        for (int j = 0; j < 4; j++)
#pragma unroll
            for (int q = 0; q < 4; q++)
                acc[t][j][q] = 0.f;

    const uint32_t a_row  = (uint32_t)(wr * 32 + (lane & 15));
    const uint32_t a_colh = (uint32_t)(lane >> 4);
    const uint32_t b_nrow = (uint32_t)(wc * 32 + (lane & 7) + ((lane >> 4) << 3));
    const uint32_t b_kh   = (uint32_t)((lane >> 3) & 1);

    uint32_t ah[2][2][4], al[2][2][4], bh[2][2][4], bl[2][2][4];

#define LOAD_K(ks_, buf_)                                                          \
    {                                                                              \
        const uint32_t kcol = (uint32_t)((ks_) * 16);                              \
        _Pragma("unroll")                                                          \
        for (int t = 0; t < 2; t++) {                                              \
            uint32_t off = (a_row + t * 16) * (BSTR * 2) + (kcol + a_colh * 8) * 2;\
            ldsm4(ah[buf_][t], sb + SM_AHI + off);                                 \
            ldsm4(al[buf_][t], sb + SM_ALO + off);                                 \
        }                                                                          \
        _Pragma("unroll")                                                          \
        for (int p = 0; p < 2; p++) {                                              \
            uint32_t off = (b_nrow + p * 16) * (BSTR * 2) + (kcol + b_kh * 8) * 2; \
            ldsm4(bh[buf_][p], sb + SM_BHI + off);                                 \
            ldsm4(bl[buf_][p], sb + SM_BLO + off);                                 \
        }                                                                          \
    }

    LOAD_K(0, 0)
#pragma unroll
    for (int ks = 0; ks < 8; ks++) {
        const int cur = ks & 1;
        if (ks < 7) LOAD_K(ks + 1, cur ^ 1)
#pragma unroll
        for (int t = 0; t < 2; t++) {
#pragma unroll
            for (int j = 0; j < 4; j++) {
                uint32_t b0h = bh[cur][j >> 1][(j & 1) * 2], b1h = bh[cur][j >> 1][(j & 1) * 2 + 1];
                uint32_t b0l = bl[cur][j >> 1][(j & 1) * 2], b1l = bl[cur][j >> 1][(j & 1) * 2 + 1];
                float* c = acc[t][j];
                mma_bf16(c, ah[cur][t], b0h, b1h);
                mma_bf16(c, ah[cur][t], b0l, b1l);
                mma_bf16(c, al[cur][t], b0h, b1h);
            }
        }
    }
#undef LOAD_K

    // ---- epilogue: bias + relu (+ residual) ----
    const float* bs = (const float*)(smem + SM_BIAS);
#pragma unroll
    for (int t = 0; t < 2; t++) {
        int row0 = m0 + wr * 32 + t * 16 + (lane >> 2);
#pragma unroll
        for (int half = 0; half < 2; half++) {
            int row = row0 + half * 8;
            if (row >= n) continue;
            float* orow = out + (size_t)row * DD;
#pragma unroll
            for (int j = 0; j < 4; j++) {
                int col = wc * 32 + j * 8 + (lane & 3) * 2;
                float v0 = acc[t][j][half * 2 + 0] + bs[col];
                float v1 = acc[t][j][half * 2 + 1] + bs[col + 1];
                v0 = v0 > 0.f ? v0 : 0.f;
                v1 = v1 > 0.f ? v1 : 0.f;
                if (MODE == 1) {
                    float2 o = *(const float2*)(orow + col);
                    v0 += o.x; v1 += o.y;
                }
                *(float2*)(orow + col) = make_float2(v0, v1);
            }
        }
    }
}

// ---------------- launcher: ONE side stream = CSR build then chunk-B chain ----------------
extern "C" void kernel_launch(void* const* d_in, const int* in_sizes, int n_in,
                              void* d_out, int out_size)
{
    const float* x  = (const float*)d_in[0];
    const void*  ei = d_in[1];
    const float* Wi = (const float*)d_in[2];
    const float* bi = (const float*)d_in[3];
    const float* Wm = (const float*)d_in[4];
    const float* bm = (const float*)d_in[5];
    const float* Wu = (const float*)d_in[6];
    const float* bu = (const float*)d_in[7];
    float* out = (float*)d_out;

    cudaFuncSetAttribute(gemm_mma_kernel<0>, cudaFuncAttributeMaxDynamicSharedMemorySize, SM_TOTAL);
    cudaFuncSetAttribute(gemm_mma_kernel<1>, cudaFuncAttributeMaxDynamicSharedMemorySize, SM_TOTAL);

    float *msg, *agg;
    __nv_bfloat16* wb;
    cudaGetSymbolAddress((void**)&msg, g_msg);
    cudaGetSymbolAddress((void**)&agg, g_agg);
    cudaGetSymbolAddress((void**)&wb, g_wb);

    const int GRID_FULL = (N_NODES + TILE_M - 1) / TILE_M;   // 1563
    const int AGG_G0 = (CHUNK_ROWS0 * 32 + 255) / 256;
    const int AGG_G1 = ((N_NODES - CHUNK_ROWS0) * 32 + 255) / 256;

    cudaStream_t s3;
    cudaStreamCreateWithFlags(&s3, cudaStreamNonBlocking);
    cudaEvent_t e0, e1, eM0, evA[ROUNDS], evB[ROUNDS];
    cudaEventCreateWithFlags(&e0, cudaEventDisableTiming);
    cudaEventCreateWithFlags(&e1, cudaEventDisableTiming);
    cudaEventCreateWithFlags(&eM0, cudaEventDisableTiming);
    for (int r = 0; r < ROUNDS; r++) {
        cudaEventCreateWithFlags(&evA[r], cudaEventDisableTiming);
        cudaEventCreateWithFlags(&evB[r], cudaEventDisableTiming);
    }

    // ---- side stream: CSR build (overlaps first GEMMs), then chunk-B chain ----
    cudaEventRecord(e0, 0);
    cudaStreamWaitEvent(s3, e0, 0);
    detect_idx_kernel<<<1, 1, 0, s3>>>((const int*)ei);
    hist_zero_kernel<<<(N_NODES + 255) / 256, 256, 0, s3>>>();
    hist_kernel<<<(N_EDGES + 255) / 256, 256, 0, s3>>>(ei);
    scan1_kernel<<<SCAN_BLOCKS, 256, 0, s3>>>();
    scan2_kernel<<<1, 128, 0, s3>>>();
    scan3_kernel<<<(N_NODES + 255) / 256, 256, 0, s3>>>();
    fill_kernel<<<(N_EDGES + 255) / 256, 256, 0, s3>>>(ei);
    cudaEventRecord(e1, s3);            // CSR ready

    // ---- main chain: weights, input GEMM, first message GEMM (full grid) ----
    conv_w_kernel<<<9, 256>>>(Wi, Wm, Wu);
    gemm_mma_kernel<0><<<GRID_FULL, 256, SM_TOTAL>>>(x, wb, bi, out, N_NODES, 0);
    gemm_mma_kernel<0><<<GRID_FULL, 256, SM_TOTAL>>>(out, wb + 32768, bm, msg, N_NODES, 0);

    cudaStreamWaitEvent(0, e1, 0);       // main: CSR must be built before aggregate A
    cudaEventRecord(eM0, 0);
    cudaStreamWaitEvent(s3, eM0, 0);     // s3: msg ready (CSR already done in s3 order)

    for (int r = 0; r < ROUNDS; r++) {
        // chain A (default stream): chunk 0 = rows [0, CHUNK_ROWS0)
        aggregate_kernel<<<AGG_G0, 256>>>(0, CHUNK_ROWS0);
        gemm_mma_kernel<1><<<CHUNK_BLKS0, 256, SM_TOTAL>>>(
            agg, wb + (size_t)(5 + r) * 32768, bu + r * DD, out, N_NODES, 0);
        if (r + 1 < ROUNDS)
            gemm_mma_kernel<0><<<CHUNK_BLKS0, 256, SM_TOTAL>>>(
                out, wb + (size_t)(2 + r) * 32768, bm + (r + 1) * DD, msg, N_NODES, 0);

        // chain B (s3): chunk 1 = rows [CHUNK_ROWS0, N_NODES)
        aggregate_kernel<<<AGG_G1, 256, 0, s3>>>(CHUNK_ROWS0, N_NODES);
        gemm_mma_kernel<1><<<CHUNK_BLKS1, 256, SM_TOTAL, s3>>>(
            agg, wb + (size_t)(5 + r) * 32768, bu + r * DD, out, N_NODES, CHUNK_BLKS0);
        if (r + 1 < ROUNDS)
            gemm_mma_kernel<0><<<CHUNK_BLKS1, 256, SM_TOTAL, s3>>>(
                out, wb + (size_t)(2 + r) * 32768, bm + (r + 1) * DD, msg, N_NODES, CHUNK_BLKS0);

        // join: next round's aggregates read ALL msg rows; final round: out complete on main
        cudaEventRecord(evB[r], s3);
        cudaStreamWaitEvent(0, evB[r], 0);
        if (r + 1 < ROUNDS) {
            cudaEventRecord(evA[r], 0);
            cudaStreamWaitEvent(s3, evA[r], 0);
        }
    }
}

// round 14
// speedup vs baseline: 1.3415x; 1.0393x over previous
#include <cuda_runtime.h>
#include <cuda_bf16.h>
#include <cstdint>

#define N_NODES 100000
#define N_EDGES 640000
#define DD      128
#define ROUNDS  4
#define SCAN_BLOCKS 98            // ceil(100000 / 1024)

// chunking: 1563 M-blocks total -> 782 (rows [0,50048)) + 781 (rows [50048,100000))
#define CHUNK_BLKS0 782
#define CHUNK_BLKS1 781
#define CHUNK_ROWS0 50048

// ---------------- scratch (allocation-free rule: __device__ globals) ----------------
__device__ __align__(16) float g_msg[N_NODES * DD];
// agg: interleaved split-bf16, per node 128 hi then 128 lo (512B/node, same as fp32)
__device__ __align__(16) __nv_bfloat16 g_aggbf[N_NODES * 2 * DD];
__device__ __align__(16) __nv_bfloat16 g_wb[9 * 2 * 16384];
__device__ int g_idx64;
// CSR build scratch
__device__ int g_deg[N_NODES];
__device__ int g_off[N_NODES + 1];
__device__ int g_cur[N_NODES];
__device__ int g_srcs[N_EDGES];
__device__ int g_bsum[SCAN_BLOCKS];
__device__ int g_boff[SCAN_BLOCKS];

// ---------------- edge_index dtype detection ----------------
__global__ void detect_idx_kernel(const int* __restrict__ ei32) {
    int is64 = 1;
    for (int i = 0; i < 32; i++) {
        int lo = ei32[2 * i];
        int hi = ei32[2 * i + 1];
        if (hi != 0 || lo < 0 || lo >= N_NODES) { is64 = 0; break; }
    }
    g_idx64 = is64;
}

// ---------------- CSR build (once per call, overlapped with first GEMMs) ----------------
__global__ void hist_zero_kernel() {
    int i = blockIdx.x * blockDim.x + threadIdx.x;
    if (i < N_NODES) g_deg[i] = 0;
}

__device__ __forceinline__ int edge_dst(const void* ei_raw, int e) {
    if (g_idx64) return (int)((const long long*)ei_raw)[N_EDGES + e];
    return ((const int*)ei_raw)[N_EDGES + e];
}
__device__ __forceinline__ int edge_src(const void* ei_raw, int e) {
    if (g_idx64) return (int)((const long long*)ei_raw)[e];
    return ((const int*)ei_raw)[e];
}

__global__ void hist_kernel(const void* __restrict__ ei_raw) {
    int e = blockIdx.x * blockDim.x + threadIdx.x;
    if (e >= N_EDGES) return;
    int d = edge_dst(ei_raw, e);
    if ((unsigned)d < N_NODES) atomicAdd(&g_deg[d], 1);
}

__global__ void scan1_kernel() {
    __shared__ int ss[256];
    int b = blockIdx.x, t = threadIdx.x;
    int base = b * 1024 + t * 4;
    int v[4], tot = 0;
#pragma unroll
    for (int j = 0; j < 4; j++) {
        v[j] = (base + j < N_NODES) ? g_deg[base + j] : 0;
        tot += v[j];
    }
    ss[t] = tot;
    __syncthreads();
#pragma unroll
    for (int off = 1; off < 256; off <<= 1) {
        int x = (t >= off) ? ss[t - off] : 0;
        __syncthreads();
        ss[t] += x;
        __syncthreads();
    }
    int run = ss[t] - tot;
#pragma unroll
    for (int j = 0; j < 4; j++) {
        if (base + j < N_NODES) g_off[base + j] = run;
        run += v[j];
    }
    if (t == 255) g_bsum[b] = ss[255];
}

__global__ void scan2_kernel() {
    __shared__ int ss[128];
    int t = threadIdx.x;
    int orig = (t < SCAN_BLOCKS) ? g_bsum[t] : 0;
    ss[t] = orig;
    __syncthreads();
#pragma unroll
    for (int off = 1; off < 128; off <<= 1) {
        int x = (t >= off) ? ss[t - off] : 0;
        __syncthreads();
        ss[t] += x;
        __syncthreads();
    }
    if (t < SCAN_BLOCKS) g_boff[t] = ss[t] - orig;
}

__global__ void scan3_kernel() {
    int i = blockIdx.x * blockDim.x + threadIdx.x;
    if (i < N_NODES) {
        int o = g_off[i] + g_boff[i >> 10];
        g_off[i] = o;
        g_cur[i] = o;
    }
    if (i == 0) g_off[N_NODES] = N_EDGES;
}

__global__ void fill_kernel(const void* __restrict__ ei_raw) {
    int e = blockIdx.x * blockDim.x + threadIdx.x;
    if (e >= N_EDGES) return;
    int d = edge_dst(ei_raw, e);
    int s = edge_src(ei_raw, e);
    if ((unsigned)d >= N_NODES || (unsigned)s >= N_NODES) return;
    int p = atomicAdd(&g_cur[d], 1);
    g_srcs[p] = s;
}

// ---------------- per-round aggregation: gather fp32 msg, write split-bf16 agg ----------------
__global__ __launch_bounds__(256) void aggregate_kernel(int node_lo, int node_hi) {
    int node = node_lo + ((blockIdx.x * 256 + threadIdx.x) >> 5);
    int lane = threadIdx.x & 31;
    if (node >= node_hi) return;
    int beg = g_off[node], end = g_off[node + 1];
    float4 acc = make_float4(0.f, 0.f, 0.f, 0.f);
    int e = beg;
    for (; e + 1 < end; e += 2) {
        int s0 = g_srcs[e], s1 = g_srcs[e + 1];
        float4 v0 = *(const float4*)(g_msg + (size_t)s0 * DD + lane * 4);
        float4 v1 = *(const float4*)(g_msg + (size_t)s1 * DD + lane * 4);
        acc.x += v0.x; acc.y += v0.y; acc.z += v0.z; acc.w += v0.w;
        acc.x += v1.x; acc.y += v1.y; acc.z += v1.z; acc.w += v1.w;
    }
    if (e < end) {
        float4 v = *(const float4*)(g_msg + (size_t)g_srcs[e] * DD + lane * 4);
        acc.x += v.x; acc.y += v.y; acc.z += v.z; acc.w += v.w;
    }
    // split fp32 -> bf16 hi/lo (producer-side; FMA pipe is idle here)
    float vv[4] = {acc.x, acc.y, acc.z, acc.w};
    __align__(8) __nv_bfloat16 h[4], l[4];
#pragma unroll
    for (int j = 0; j < 4; j++) {
        h[j] = __float2bfloat16(vv[j]);
        l[j] = __float2bfloat16(vv[j] - __bfloat162float(h[j]));
    }
    __nv_bfloat16* base = g_aggbf + (size_t)node * (2 * DD);
    *(uint2*)(base + lane * 4)      = *(const uint2*)h;   // hi image [0,128)
    *(uint2*)(base + DD + lane * 4) = *(const uint2*)l;   // lo image [128,256)
}

// ---------------- weight precompute: transpose + bf16 split ----------------
__global__ void conv_w_kernel(const float* __restrict__ Wi,
                              const float* __restrict__ Wm,
                              const float* __restrict__ Wu) {
    int m = blockIdx.x;  // 0..8
    const float* W = (m == 0) ? Wi : (m <= 4 ? Wm + (m - 1) * DD * DD : Wu + (m - 5) * DD * DD);
    __nv_bfloat16* hi = g_wb + (size_t)m * 32768;
    __nv_bfloat16* lo = hi + 16384;
    for (int i = threadIdx.x; i < 2048; i += blockDim.x) {
        int nrow = i >> 4;
        int k8   = (i & 15) * 8;
        __align__(16) __nv_bfloat16 h[8], l[8];
#pragma unroll
        for (int j = 0; j < 8; j++) {
            float w = W[(size_t)(k8 + j) * DD + nrow];   // B[n][k] = W[k][n]
            __nv_bfloat16 hb = __float2bfloat16(w);
            h[j] = hb;
            l[j] = __float2bfloat16(w - __bfloat162float(hb));
        }
        *(uint4*)(hi + nrow * DD + k8) = *(const uint4*)h;
        *(uint4*)(lo + nrow * DD + k8) = *(const uint4*)l;
    }
}

// ---------------- helpers (base-target PTX only) ----------------
__device__ __forceinline__ uint32_t smem_u32(const void* p) {
    uint32_t a;
    asm("{ .reg .u64 t; cvta.to.shared.u64 t, %1; cvt.u32.u64 %0, t; }" : "=r"(a) : "l"(p));
    return a;
}
__device__ __forceinline__ void ldsm4(uint32_t* r, uint32_t addr) {
    asm volatile("ldmatrix.sync.aligned.m8n8.x4.shared.b16 {%0,%1,%2,%3}, [%4];"
                 : "=r"(r[0]), "=r"(r[1]), "=r"(r[2]), "=r"(r[3]) : "r"(addr));
}
__device__ __forceinline__ void mma_bf16(float* c,
                                         const uint32_t* a, uint32_t b0, uint32_t b1) {
    asm volatile(
        "mma.sync.aligned.m16n8k16.row.col.f32.bf16.bf16.f32 "
        "{%0,%1,%2,%3}, {%4,%5,%6,%7}, {%8,%9}, {%0,%1,%2,%3};"
        : "+f"(c[0]), "+f"(c[1]), "+f"(c[2]), "+f"(c[3])
        : "r"(a[0]), "r"(a[1]), "r"(a[2]), "r"(a[3]), "r"(b0), "r"(b1));
}
__device__ __forceinline__ void cp_async16(uint32_t smem_addr, const void* gptr) {
    asm volatile("cp.async.ca.shared.global [%0], [%1], 16;"
                 :: "r"(smem_addr), "l"(gptr) : "memory");
}
__device__ __forceinline__ void cp_async16z(uint32_t smem_addr, const void* gptr, unsigned srcsz) {
    asm volatile("cp.async.ca.shared.global [%0], [%1], 16, %2;"
                 :: "r"(smem_addr), "l"(gptr), "r"(srcsz) : "memory");
}

// ---------------- GEMM: 64x128 tile, 2 CTAs/SM, pipelined frags ----------------
#define TILE_M  64
#define BSTR    136
#define A_TB    (TILE_M * BSTR * 2)       // 17408 B
#define B_TB    (128 * BSTR * 2)          // 34816 B
#define SM_BIAS 0
#define SM_AHI  512
#define SM_ALO  (SM_AHI + A_TB)
#define SM_BHI  (SM_ALO + A_TB)
#define SM_BLO  (SM_BHI + B_TB)
#define SM_TOTAL (SM_BLO + B_TB)          // 104960 B -> 2 CTAs/SM

// MODE: 0 fresh / 1 residual.  ASRC: 0 = fp32 A (convert in-kernel),
// 1 = interleaved split-bf16 A (hi at row*256, lo at row*256+128) via cp.async
template <int MODE, int ASRC>
__global__ __launch_bounds__(256, 2) void gemm_mma_kernel(
    const float* __restrict__ A,
    const __nv_bfloat16* __restrict__ abf,
    const __nv_bfloat16* __restrict__ wb,
    const float* __restrict__ bias,
    float* __restrict__ out,
    int n, int mb0)
{
    extern __shared__ char smem[];
    const uint32_t sb = smem_u32(smem);
    const int tid = threadIdx.x, wid = tid >> 5, lane = tid & 31;
    const int wr = wid & 1, wc = wid >> 1;      // warp grid 2 (M) x 4 (N)
    const int m0 = (blockIdx.x + mb0) * TILE_M;

    if (tid < 128) *(float*)(smem + SM_BIAS + tid * 4) = bias[tid];

    // ---- B tiles via cp.async ----
    {
        const uint4* srch = (const uint4*)wb;
        const uint4* srcl = (const uint4*)(wb + 16384);
#pragma unroll
        for (int i = tid; i < 2048; i += 256) {
            int row = i >> 4, c = i & 15;
            uint32_t doff = (uint32_t)(row * (BSTR * 2) + c * 16);
            cp_async16(sb + SM_BHI + doff, srch + row * 16 + c);
            cp_async16(sb + SM_BLO + doff, srcl + row * 16 + c);
        }
    }

    if (ASRC == 1) {
        // ---- A tiles: pure cp.async of interleaved split-bf16 (zfill on tail) ----
#pragma unroll
        for (int i = tid; i < 1024; i += 256) {
            int r = i >> 4, c = i & 15;      // c: 16B chunk (8 bf16) within 256B image
            int row = m0 + r;
            int crow = row < n ? row : 0;
            unsigned sz = (row < n) ? 16u : 0u;
            uint32_t doff = (uint32_t)(r * (BSTR * 2) + c * 16);
            const __nv_bfloat16* base = abf + (size_t)crow * (2 * DD) + c * 8;
            cp_async16z(sb + SM_AHI + doff, base, sz);
            cp_async16z(sb + SM_ALO + doff, base + DD, sz);
        }
        asm volatile("cp.async.commit_group;" ::: "memory");
    } else {
        asm volatile("cp.async.commit_group;" ::: "memory");
        // ---- A tile: fp32 -> bf16 hi/lo in-kernel ----
        for (int i = tid; i < TILE_M * 16; i += 256) {
            int r  = i >> 4;
            int k8 = (i & 15) * 8;
            int row = m0 + r;
            float v[8];
            if (row < n) {
                float4 u0 = *(const float4*)(A + (size_t)row * DD + k8);
                float4 u1 = *(const float4*)(A + (size_t)row * DD + k8 + 4);
                v[0] = u0.x; v[1] = u0.y; v[2] = u0.z; v[3] = u0.w;
                v[4] = u1.x; v[5] = u1.y; v[6] = u1.z; v[7] = u1.w;
            } else {
#pragma unroll
                for (int j = 0; j < 8; j++) v[j] = 0.f;
            }
            __align__(16) __nv_bfloat16 h[8], l[8];
#pragma unroll
            for (int j = 0; j < 8; j++) {
                __nv_bfloat16 hb = __float2bfloat16(v[j]);
                h[j] = hb;
                l[j] = __float2bfloat16(v[j] - __bfloat162float(hb));
            }
            *(uint4*)(smem + SM_AHI + r * (BSTR * 2) + k8 * 2) = *(const uint4*)h;
            *(uint4*)(smem + SM_ALO + r * (BSTR * 2) + k8 * 2) = *(const uint4*)l;
        }
    }
    asm volatile("cp.async.wait_group 0;" ::: "memory");
    __syncthreads();

    // ---- mainloop: 8 k-steps, double-buffered frags ----
    float acc[2][4][4];
#pragma unroll
    for (int t = 0; t < 2; t++)
#pragma unroll
        for (int j = 0; j < 4; j++)
#pragma unroll
            for (int q = 0; q < 4; q++)
                acc[t][j][q] = 0.f;

    const uint32_t a_row  = (uint32_t)(wr * 32 + (lane & 15));
    const uint32_t a_colh = (uint32_t)(lane >> 4);
    const uint32_t b_nrow = (uint32_t)(wc * 32 + (lane & 7) + ((lane >> 4) << 3));
    const uint32_t b_kh   = (uint32_t)((lane >> 3) & 1);

    uint32_t ah[2][2][4], al[2][2][4], bh[2][2][4], bl[2][2][4];

#define LOAD_K(ks_, buf_)                                                          \
    {                                                                              \
        const uint32_t kcol = (uint32_t)((ks_) * 16);                              \
        _Pragma("unroll")                                                          \
        for (int t = 0; t < 2; t++) {                                              \
            uint32_t off = (a_row + t * 16) * (BSTR * 2) + (kcol + a_colh * 8) * 2;\
            ldsm4(ah[buf_][t], sb + SM_AHI + off);                                 \
            ldsm4(al[buf_][t], sb + SM_ALO + off);                                 \
        }                                                                          \
        _Pragma("unroll")                                                          \
        for (int p = 0; p < 2; p++) {                                              \
            uint32_t off = (b_nrow + p * 16) * (BSTR * 2) + (kcol + b_kh * 8) * 2; \
            ldsm4(bh[buf_][p], sb + SM_BHI + off);                                 \
            ldsm4(bl[buf_][p], sb + SM_BLO + off);                                 \
        }                                                                          \
    }

    LOAD_K(0, 0)
#pragma unroll
    for (int ks = 0; ks < 8; ks++) {
        const int cur = ks & 1;
        if (ks < 7) LOAD_K(ks + 1, cur ^ 1)
#pragma unroll
        for (int t = 0; t < 2; t++) {
#pragma unroll
            for (int j = 0; j < 4; j++) {
                uint32_t b0h = bh[cur][j >> 1][(j & 1) * 2], b1h = bh[cur][j >> 1][(j & 1) * 2 + 1];
                uint32_t b0l = bl[cur][j >> 1][(j & 1) * 2], b1l = bl[cur][j >> 1][(j & 1) * 2 + 1];
                float* c = acc[t][j];
                mma_bf16(c, ah[cur][t], b0h, b1h);
                mma_bf16(c, ah[cur][t], b0l, b1l);
                mma_bf16(c, al[cur][t], b0h, b1h);
            }
        }
    }
#undef LOAD_K

    // ---- epilogue: bias + relu (+ residual) ----
    const float* bs = (const float*)(smem + SM_BIAS);
#pragma unroll
    for (int t = 0; t < 2; t++) {
        int row0 = m0 + wr * 32 + t * 16 + (lane >> 2);
#pragma unroll
        for (int half = 0; half < 2; half++) {
            int row = row0 + half * 8;
            if (row >= n) continue;
            float* orow = out + (size_t)row * DD;
#pragma unroll
            for (int j = 0; j < 4; j++) {
                int col = wc * 32 + j * 8 + (lane & 3) * 2;
                float v0 = acc[t][j][half * 2 + 0] + bs[col];
                float v1 = acc[t][j][half * 2 + 1] + bs[col + 1];
                v0 = v0 > 0.f ? v0 : 0.f;
                v1 = v1 > 0.f ? v1 : 0.f;
                if (MODE == 1) {
                    float2 o = *(const float2*)(orow + col);
                    v0 += o.x; v1 += o.y;
                }
                *(float2*)(orow + col) = make_float2(v0, v1);
            }
        }
    }
}

// ---------------- launcher: ONE side stream = CSR build then chunk-B chain ----------------
extern "C" void kernel_launch(void* const* d_in, const int* in_sizes, int n_in,
                              void* d_out, int out_size)
{
    const float* x  = (const float*)d_in[0];
    const void*  ei = d_in[1];
    const float* Wi = (const float*)d_in[2];
    const float* bi = (const float*)d_in[3];
    const float* Wm = (const float*)d_in[4];
    const float* bm = (const float*)d_in[5];
    const float* Wu = (const float*)d_in[6];
    const float* bu = (const float*)d_in[7];
    float* out = (float*)d_out;

    cudaFuncSetAttribute(gemm_mma_kernel<0,0>, cudaFuncAttributeMaxDynamicSharedMemorySize, SM_TOTAL);
    cudaFuncSetAttribute(gemm_mma_kernel<1,1>, cudaFuncAttributeMaxDynamicSharedMemorySize, SM_TOTAL);

    float* msg;
    __nv_bfloat16 *wb, *aggbf;
    cudaGetSymbolAddress((void**)&msg, g_msg);
    cudaGetSymbolAddress((void**)&wb, g_wb);
    cudaGetSymbolAddress((void**)&aggbf, g_aggbf);

    const int GRID_FULL = (N_NODES + TILE_M - 1) / TILE_M;   // 1563
    const int AGG_G0 = (CHUNK_ROWS0 * 32 + 255) / 256;
    const int AGG_G1 = ((N_NODES - CHUNK_ROWS0) * 32 + 255) / 256;

    cudaStream_t s3;
    cudaStreamCreateWithFlags(&s3, cudaStreamNonBlocking);
    cudaEvent_t e0, e1, eM0, evA[ROUNDS], evB[ROUNDS];
    cudaEventCreateWithFlags(&e0, cudaEventDisableTiming);
    cudaEventCreateWithFlags(&e1, cudaEventDisableTiming);
    cudaEventCreateWithFlags(&eM0, cudaEventDisableTiming);
    for (int r = 0; r < ROUNDS; r++) {
        cudaEventCreateWithFlags(&evA[r], cudaEventDisableTiming);
        cudaEventCreateWithFlags(&evB[r], cudaEventDisableTiming);
    }

    // ---- side stream: CSR build (overlaps first GEMMs), then chunk-B chain ----
    cudaEventRecord(e0, 0);
    cudaStreamWaitEvent(s3, e0, 0);
    detect_idx_kernel<<<1, 1, 0, s3>>>((const int*)ei);
    hist_zero_kernel<<<(N_NODES + 255) / 256, 256, 0, s3>>>();
    hist_kernel<<<(N_EDGES + 255) / 256, 256, 0, s3>>>(ei);
    scan1_kernel<<<SCAN_BLOCKS, 256, 0, s3>>>();
    scan2_kernel<<<1, 128, 0, s3>>>();
    scan3_kernel<<<(N_NODES + 255) / 256, 256, 0, s3>>>();
    fill_kernel<<<(N_EDGES + 255) / 256, 256, 0, s3>>>(ei);
    cudaEventRecord(e1, s3);            // CSR ready

    // ---- main chain: weights, input GEMM, first message GEMM (full grid) ----
    conv_w_kernel<<<9, 256>>>(Wi, Wm, Wu);
    gemm_mma_kernel<0,0><<<GRID_FULL, 256, SM_TOTAL>>>(x, nullptr, wb, bi, out, N_NODES, 0);
    gemm_mma_kernel<0,0><<<GRID_FULL, 256, SM_TOTAL>>>(out, nullptr, wb + 32768, bm, msg, N_NODES, 0);

    cudaStreamWaitEvent(0, e1, 0);       // main: CSR must be built before aggregate A
    cudaEventRecord(eM0, 0);
    cudaStreamWaitEvent(s3, eM0, 0);     // s3: msg ready (CSR already done in s3 order)

    for (int r = 0; r < ROUNDS; r++) {
        // chain A (default stream): chunk 0 = rows [0, CHUNK_ROWS0)
        aggregate_kernel<<<AGG_G0, 256>>>(0, CHUNK_ROWS0);
        gemm_mma_kernel<1,1><<<CHUNK_BLKS0, 256, SM_TOTAL>>>(
            nullptr, aggbf, wb + (size_t)(5 + r) * 32768, bu + r * DD, out, N_NODES, 0);
        if (r + 1 < ROUNDS)
            gemm_mma_kernel<0,0><<<CHUNK_BLKS0, 256, SM_TOTAL>>>(
                out, nullptr, wb + (size_t)(2 + r) * 32768, bm + (r + 1) * DD, msg, N_NODES, 0);

        // chain B (s3): chunk 1 = rows [CHUNK_ROWS0, N_NODES)
        aggregate_kernel<<<AGG_G1, 256, 0, s3>>>(CHUNK_ROWS0, N_NODES);
        gemm_mma_kernel<1,1><<<CHUNK_BLKS1, 256, SM_TOTAL, s3>>>(
            nullptr, aggbf, wb + (size_t)(5 + r) * 32768, bu + r * DD, out, N_NODES, CHUNK_BLKS0);
        if (r + 1 < ROUNDS)
            gemm_mma_kernel<0,0><<<CHUNK_BLKS1, 256, SM_TOTAL, s3>>>(
                out, nullptr, wb + (size_t)(2 + r) * 32768, bm + (r + 1) * DD, msg, N_NODES, CHUNK_BLKS0);

        // join: next round's aggregates read ALL msg rows; final round: out complete on main
        cudaEventRecord(evB[r], s3);
        cudaStreamWaitEvent(0, evB[r], 0);
        if (r + 1 < ROUNDS) {
            cudaEventRecord(evA[r], 0);
            cudaStreamWaitEvent(s3, evA[r], 0);
        }
    }
}